// round 1
// baseline (speedup 1.0000x reference)
#include <cuda_runtime.h>
#include <math.h>

// Problem constants
#define BN   64
#define HW   784          // 28*28
#define CN   512
#define S    8            // spatial splits
#define HWP  98           // HW / S

// Scratch for partial argmax results (device globals: allocation-free)
__device__ float g_pval[BN * S * CN];
__device__ int   g_pidx[BN * S * CN];

// ---------------------------------------------------------------------------
// Kernel 1: partial argmax over a 98-position spatial slice, per (b, c).
// blockIdx.x = batch, blockIdx.y = split, threadIdx.x = channel.
// x[b, hw, c] reads are fully coalesced (warp reads 128B contiguous in c).
// ---------------------------------------------------------------------------
__global__ void __launch_bounds__(CN) argmax_partial_kernel(const float* __restrict__ x) {
    const int b = blockIdx.x;
    const int s = blockIdx.y;
    const int c = threadIdx.x;

    const size_t base = ((size_t)b * HW + (size_t)s * HWP) * CN + c;

    float best = -INFINITY;
    int   bidx = s * HWP;   // default (never kept unless first compare wins)

    #pragma unroll 7
    for (int i = 0; i < HWP; ++i) {
        float v = x[base + (size_t)i * CN];
        if (v > best) {          // strict > + ascending i => first occurrence
            best = v;
            bidx = s * HWP + i;
        }
    }

    const int o = (b * S + s) * CN + c;
    g_pval[o] = best;
    g_pidx[o] = bidx;
}

// ---------------------------------------------------------------------------
// Kernel 2: combine partials (prologue) then
//   out[b,hw,c] = relu(x[b,hw,c] * t_p[b, idx[b,c], hw])
// Thread owns a fixed (b,c): x/out coalesced along c; template row is a
// per-thread contiguous stream (L1 catches the 8-iterations-per-sector reuse).
// ---------------------------------------------------------------------------
__global__ void __launch_bounds__(CN) apply_kernel(const float* __restrict__ x,
                                                   const float* __restrict__ tp,
                                                   float* __restrict__ out) {
    const int b = blockIdx.x;
    const int s = blockIdx.y;
    const int c = threadIdx.x;

    // Combine the 8 partials: ascending split order + strict > keeps the
    // earliest spatial index on equal maxima (matches jnp.argmax).
    float best = -INFINITY;
    int   idx  = 0;
    #pragma unroll
    for (int p = 0; p < S; ++p) {
        const int o = (b * S + p) * CN + c;
        float v = g_pval[o];
        if (v > best) {
            best = v;
            idx  = g_pidx[o];
        }
    }

    // Selected template row: t_p[b, idx, 0..783] (contiguous 784 floats)
    const float* __restrict__ trow = tp + ((size_t)b * HW + (size_t)idx) * HW;

    const int    hw0  = s * HWP;
    const size_t base = ((size_t)b * HW + (size_t)hw0) * CN + c;

    #pragma unroll 7
    for (int i = 0; i < HWP; ++i) {
        float xv = x[base + (size_t)i * CN];
        float tv = trow[hw0 + i];
        out[base + (size_t)i * CN] = fmaxf(xv * tv, 0.0f);
    }
}

// ---------------------------------------------------------------------------
// Launch: inputs are [x, t_p] per metadata order; output fp32 [64,28,28,512].
// Graph-capturable: two plain kernel launches, no sync, no allocation.
// ---------------------------------------------------------------------------
extern "C" void kernel_launch(void* const* d_in, const int* in_sizes, int n_in,
                              void* d_out, int out_size) {
    (void)in_sizes; (void)n_in; (void)out_size;
    const float* x  = (const float*)d_in[0];
    const float* tp = (const float*)d_in[1];
    float*       out = (float*)d_out;

    dim3 grid(BN, S);
    argmax_partial_kernel<<<grid, CN>>>(x);
    apply_kernel<<<grid, CN>>>(x, tp, out);
}

// round 2
// speedup vs baseline: 1.3315x; 1.3315x over previous
#include <cuda_runtime.h>
#include <math.h>

// Problem constants
#define BN   64
#define HW   784          // 28*28
#define CN   512
#define S    7            // spatial splits (112*4 bytes = 448 ≡ 0 mod 16 → float4-aligned)
#define HWP  112          // HW / S
#define HWP4 28           // HWP / 4

// Scratch for partial argmax results (device globals: allocation-free)
__device__ float g_pval[BN * S * CN];
__device__ int   g_pidx[BN * S * CN];

// ---------------------------------------------------------------------------
// Kernel 1: partial argmax over a 112-position spatial slice, per (b, c).
// blockIdx.x = batch, blockIdx.y = split, threadIdx.x = channel.
// Coalesced 2KB row reads along c.
// ---------------------------------------------------------------------------
__global__ void __launch_bounds__(CN) argmax_partial_kernel(const float* __restrict__ x) {
    const int b = blockIdx.x;
    const int s = blockIdx.y;
    const int c = threadIdx.x;

    const size_t base = ((size_t)b * HW + (size_t)s * HWP) * CN + c;

    float best = -INFINITY;
    int   bidx = s * HWP;

    #pragma unroll 8
    for (int i = 0; i < HWP; ++i) {
        float v = x[base + (size_t)i * CN];
        if (v > best) {          // strict > + ascending i => first occurrence
            best = v;
            bidx = s * HWP + i;
        }
    }

    const int o = (b * S + s) * CN + c;
    g_pval[o] = best;
    g_pidx[o] = bidx;
}

// ---------------------------------------------------------------------------
// Kernel 2: combine partials, then
//   out[b,hw,c] = relu(x[b,hw,c] * t_p[b, idx[b,c], hw])
// Template stream is read as float4 (4 hw values per request) to cut the
// divergent-gather L1 wavefront count 4x. x/out stay coalesced along c.
// ---------------------------------------------------------------------------
__global__ void __launch_bounds__(CN) apply_kernel(const float* __restrict__ x,
                                                   const float* __restrict__ tp,
                                                   float* __restrict__ out) {
    const int b = blockIdx.x;
    const int s = blockIdx.y;
    const int c = threadIdx.x;

    // Combine the 7 partials: ascending split order + strict > keeps the
    // earliest spatial index on equal maxima (matches jnp.argmax).
    float best = -INFINITY;
    int   idx  = 0;
    #pragma unroll
    for (int p = 0; p < S; ++p) {
        const int o = (b * S + p) * CN + c;
        float v = g_pval[o];
        if (v > best) {
            best = v;
            idx  = g_pidx[o];
        }
    }

    // Selected template row slice: t_p[b, idx, s*112 .. s*112+111]
    // Row pitch 784*4 = 3136 B and slice offset 112*4 = 448 B are both
    // 16B-multiples, and tp base is 256B-aligned -> float4-safe.
    const float4* __restrict__ trow4 =
        (const float4*)(tp + ((size_t)b * HW + (size_t)idx) * HW + s * HWP);

    const size_t base = ((size_t)b * HW + (size_t)s * HWP) * CN + c;

    #pragma unroll 4
    for (int j = 0; j < HWP4; ++j) {
        const float4 t4 = __ldg(trow4 + j);
        const size_t o  = base + (size_t)(4 * j) * CN;

        float x0 = x[o];
        float x1 = x[o + (size_t)CN];
        float x2 = x[o + (size_t)(2 * CN)];
        float x3 = x[o + (size_t)(3 * CN)];

        out[o]                    = fmaxf(x0 * t4.x, 0.0f);
        out[o + (size_t)CN]       = fmaxf(x1 * t4.y, 0.0f);
        out[o + (size_t)(2 * CN)] = fmaxf(x2 * t4.z, 0.0f);
        out[o + (size_t)(3 * CN)] = fmaxf(x3 * t4.w, 0.0f);
    }
}

// ---------------------------------------------------------------------------
// Launch: inputs [x, t_p]; output fp32 [64,28,28,512]. Graph-capturable.
// ---------------------------------------------------------------------------
extern "C" void kernel_launch(void* const* d_in, const int* in_sizes, int n_in,
                              void* d_out, int out_size) {
    (void)in_sizes; (void)n_in; (void)out_size;
    const float* x   = (const float*)d_in[0];
    const float* tp  = (const float*)d_in[1];
    float*       out = (float*)d_out;

    dim3 grid(BN, S);
    argmax_partial_kernel<<<grid, CN>>>(x);
    apply_kernel<<<grid, CN>>>(x, tp, out);
}